// round 8
// baseline (speedup 1.0000x reference)
#include <cuda_runtime.h>
#include <math_constants.h>

#define THREADS_MAIN 256    // 8 warps per block
#define BLOCKS_PER_SM 2

__device__ __forceinline__ void f32x2_add(unsigned long long& acc, unsigned long long v) {
    asm("add.rn.f32x2 %0, %0, %1;" : "+l"(acc) : "l"(v));
}
__device__ __forceinline__ float2 unpack2(unsigned long long v) {
    float a, b;
    asm("mov.b64 {%0,%1}, %2;" : "=f"(a), "=f"(b) : "l"(v));
    return make_float2(a, b);
}

// ---------------------------------------------------------------------------
// Single-kernel segmented mean+max with ownership partitioning:
// a warp owns every segment whose FIRST atom lies in its chunk. It skips
// leading atoms owned by an earlier warp (membership-only, ballot-based) and
// extends past its chunk end to finish its last segment. Every feature row is
// read exactly once chip-wide; every output row written exactly once.
// ---------------------------------------------------------------------------
__global__ void __launch_bounds__(THREADS_MAIN)
gg_main(const float* __restrict__ feat,
        const int*   __restrict__ mem,
        float*       __restrict__ out,
        int n_atoms, int chunk) {
    const int lane = threadIdx.x & 31;
    const int wg   = (blockIdx.x * blockDim.x + threadIdx.x) >> 5;
    long long astart = (long long)wg * chunk;
    if (astart >= n_atoms) return;
    long long aend = astart + chunk;
    if (aend > n_atoms) aend = n_atoms;

    const ulonglong2* __restrict__ frow = (const ulonglong2*)feat;  // 32 per row
    long long a = astart;

    // ---- cooperative skip: advance past the segment continuing from the
    //      previous chunk (owned by an earlier warp). Membership reads only.
    if (astart > 0) {
        int prev = __ldg(mem + astart - 1);
        for (;;) {
            long long idx = a + lane;
            int mv = (idx < aend) ? __ldg(mem + idx) : (prev + 1);  // sentinel = changed
            unsigned nb = __ballot_sync(0xffffffffu, mv != prev);
            if (nb) { a += __ffs(nb) - 1; break; }
            a += 32;
        }
        if (a >= aend) return;   // whole chunk belongs to an earlier warp's segment
    }

    int seg = __ldg(mem + a);

    unsigned long long s01 = 0, s23 = 0;   // packed f32x2 sums
    float4 m = make_float4(-CUDART_INF_F, -CUDART_INF_F, -CUDART_INF_F, -CUDART_INF_F);
    int cnt = 0;

    auto store_full = [&](int sg) {
        float2 x = unpack2(s01), y = unpack2(s23);
        float r = 1.0f / (float)cnt;
        float* om = out + (size_t)sg * 256 + lane * 4;
        *(float4*)om         = make_float4(x.x * r, x.y * r, y.x * r, y.y * r);
        *(float4*)(om + 128) = m;
    };
    auto reset = [&]() {
        s01 = 0; s23 = 0;
        m = make_float4(-CUDART_INF_F, -CUDART_INF_F, -CUDART_INF_F, -CUDART_INF_F);
        cnt = 0;
    };
    auto accum = [&](ulonglong2 v) {
        f32x2_add(s01, v.x);
        f32x2_add(s23, v.y);
        float2 x = unpack2(v.x), y = unpack2(v.y);
        m.x = fmaxf(m.x, x.x); m.y = fmaxf(m.y, x.y);
        m.z = fmaxf(m.z, y.x); m.w = fmaxf(m.w, y.y);
    };

    // ---- bulk loop over own chunk (scalar membership loads: alignment-free)
    for (; a + 8 <= aend; a += 8) {
        int mbs[8];
#pragma unroll
        for (int u = 0; u < 8; ++u) mbs[u] = __ldg(mem + a + u);
        ulonglong2 vv[8];
#pragma unroll
        for (int u = 0; u < 8; ++u) vv[u] = __ldg(&frow[(a + u) * 32 + lane]);

        if (mbs[0] == mbs[7]) {
            // whole 8-batch one segment (sorted membership)
            if (mbs[0] != seg) { store_full(seg); reset(); seg = mbs[0]; }
#pragma unroll
            for (int u = 0; u < 8; ++u) accum(vv[u]);
            cnt += 8;
        } else {
#pragma unroll
            for (int u = 0; u < 8; ++u) {
                if (mbs[u] != seg) { store_full(seg); reset(); seg = mbs[u]; }
                accum(vv[u]);
                ++cnt;
            }
        }
    }
    // ---- in-chunk scalar tail
    for (; a < aend; ++a) {
        int mb = __ldg(mem + a);
        ulonglong2 v = __ldg(&frow[a * 32 + lane]);
        if (mb != seg) { store_full(seg); reset(); seg = mb; }
        accum(v);
        ++cnt;
    }
    // ---- extension past chunk end: finish the owned last segment
    //      (ballot windows of 32; these atoms are skipped by later warps)
    while (a < n_atoms) {
        long long idx = a + lane;
        int mv = (idx < n_atoms) ? __ldg(mem + idx) : (seg + 1);    // sentinel = changed
        unsigned nb = __ballot_sync(0xffffffffu, mv != seg);
        int k = nb ? (__ffs(nb) - 1) : 32;
#pragma unroll 4
        for (int u = 0; u < k; ++u)
            accum(__ldg(&frow[(a + u) * 32 + lane]));
        cnt += k;
        a   += k;
        if (k < 32) break;
    }
    store_full(seg);
}

// ---------------------------------------------------------------------------
extern "C" void kernel_launch(void* const* d_in, const int* in_sizes, int n_in,
                              void* d_out, int out_size) {
    const float* feat = (const float*)d_in[0];
    const int*   mem  = (const int*)d_in[1];
    float*       out  = (float*)d_out;

    int n_atoms = in_sizes[1];          // membership element count

    // Exactly-balanced single wave: SM_count * BLOCKS_PER_SM blocks, 8 warps each.
    int sm_count = 152;
    cudaDeviceGetAttribute(&sm_count, cudaDevAttrMultiProcessorCount, 0);
    int nblocks = sm_count * BLOCKS_PER_SM;
    long long nwarps = (long long)nblocks * (THREADS_MAIN / 32);
    long long chunk_ll = ((long long)n_atoms + nwarps - 1) / nwarps;
    int chunk = (int)((chunk_ll + 7) / 8) * 8;   // multiple of 8

    gg_main<<<nblocks, THREADS_MAIN>>>(feat, mem, out, n_atoms, chunk);
}

// round 9
// speedup vs baseline: 1.0280x; 1.0280x over previous
#include <cuda_runtime.h>
#include <math_constants.h>

#define THREADS_MAIN 256    // 8 warps per block
#define BLOCKS_PER_SM 3
#define MAXW 4096           // max warps supported (grid capped accordingly)

// Per-warp boundary partial records (fully rewritten every launch).
__device__ float4 g_sH[MAXW][32];   // head partial sums
__device__ float4 g_mH[MAXW][32];   // head partial maxs
__device__ int    g_cH[MAXW];       // head partial count
__device__ int    g_segH[MAXW];     // head segment id (-1 = none)
__device__ int    g_ptH[MAXW];      // head is pass-through (open both ends)
__device__ float4 g_sT[MAXW][32];   // tail partial sums (owner records)
__device__ float4 g_mT[MAXW][32];
__device__ int    g_cT[MAXW];
__device__ int    g_segT[MAXW];     // tail segment id (-1 = none)

__device__ __forceinline__ void f32x2_add(unsigned long long& acc, unsigned long long v) {
    asm("add.rn.f32x2 %0, %0, %1;" : "+l"(acc) : "l"(v));
}
__device__ __forceinline__ float2 unpack2(unsigned long long v) {
    float a, b;
    asm("mov.b64 {%0,%1}, %2;" : "=f"(a), "=f"(b) : "l"(v));
    return make_float2(a, b);
}

// ---------------------------------------------------------------------------
// Main: warp-per-chunk segmented scan. Lane l owns features [4l,4l+4).
// Interior segments -> direct full store (mean divided in place).
// Head partial buffered in registers; all boundary records published at the
// end (L2-hot for gg_combine).
// ---------------------------------------------------------------------------
__global__ void __launch_bounds__(THREADS_MAIN, BLOCKS_PER_SM)
gg_main(const float* __restrict__ feat,
        const int*   __restrict__ mem,
        float*       __restrict__ out,
        int n_atoms, int chunk) {
    const int lane = threadIdx.x & 31;
    const int wg   = (blockIdx.x * blockDim.x + threadIdx.x) >> 5;
    long long astart = (long long)wg * chunk;
    if (astart >= n_atoms) {
        if (lane == 0) { g_segH[wg] = -1; g_segT[wg] = -1; }
        return;
    }
    long long aend = astart + chunk;
    if (aend > n_atoms) aend = n_atoms;

    const ulonglong2* __restrict__ frow = (const ulonglong2*)feat;  // 32 per row

    int  seg = __ldg(mem + astart);
    bool began_inside = (astart == 0) || (__ldg(mem + astart - 1) != seg);

    unsigned long long s01 = 0, s23 = 0;   // packed f32x2 sums
    float4 m = make_float4(-CUDART_INF_F, -CUDART_INF_F, -CUDART_INF_F, -CUDART_INF_F);
    int cnt = 0;

    // Head partial buffered in registers until the end.
    int    hseg = -1, hpt = 0, hcnt = 0;
    float4 hsum = make_float4(0.f, 0.f, 0.f, 0.f);
    float4 hmax = hsum;

    auto store_full = [&](int sg) {
        float2 a = unpack2(s01), b = unpack2(s23);
        float r = 1.0f / (float)cnt;
        float* om = out + (size_t)sg * 256 + lane * 4;
        *(float4*)om         = make_float4(a.x * r, a.y * r, b.x * r, b.y * r);
        *(float4*)(om + 128) = m;
    };
    auto buffer_head = [&](int sg, int pt) {
        float2 a = unpack2(s01), b = unpack2(s23);
        hsum = make_float4(a.x, a.y, b.x, b.y);
        hmax = m; hcnt = cnt; hseg = sg; hpt = pt;
    };
    auto flush_mid = [&](int sg) {       // segment ended inside the chunk
        if (began_inside) store_full(sg);
        else              buffer_head(sg, 0);
        began_inside = true;
    };
    auto reset = [&]() {
        s01 = 0; s23 = 0;
        m = make_float4(-CUDART_INF_F, -CUDART_INF_F, -CUDART_INF_F, -CUDART_INF_F);
        cnt = 0;
    };
    auto accum = [&](ulonglong2 v) {
        f32x2_add(s01, v.x);
        f32x2_add(s23, v.y);
        float2 a = unpack2(v.x), b = unpack2(v.y);
        m.x = fmaxf(m.x, a.x); m.y = fmaxf(m.y, a.y);
        m.z = fmaxf(m.z, b.x); m.w = fmaxf(m.w, b.y);
    };

    long long a = astart;
    for (; a + 8 <= aend; a += 8) {
        int4 mb0 = *(const int4*)(mem + a);
        int4 mb1 = *(const int4*)(mem + a + 4);
        ulonglong2 vv[8];
#pragma unroll
        for (int u = 0; u < 8; ++u)
            vv[u] = __ldg(&frow[(a + u) * 32 + lane]);

        if (mb0.x == mb1.w) {
            // whole 8-batch is one segment (membership sorted)
            if (mb0.x != seg) { flush_mid(seg); seg = mb0.x; reset(); }
#pragma unroll
            for (int u = 0; u < 8; ++u) accum(vv[u]);
            cnt += 8;
        } else {
            int mbs[8] = {mb0.x, mb0.y, mb0.z, mb0.w, mb1.x, mb1.y, mb1.z, mb1.w};
#pragma unroll
            for (int u = 0; u < 8; ++u) {
                if (mbs[u] != seg) { flush_mid(seg); seg = mbs[u]; reset(); }
                accum(vv[u]);
                ++cnt;
            }
        }
    }
    for (; a < aend; ++a) {     // scalar tail (last active warp only)
        int mb = __ldg(mem + a);
        ulonglong2 v = __ldg(&frow[a * 32 + lane]);
        if (mb != seg) { flush_mid(seg); seg = mb; reset(); }
        accum(v);
        ++cnt;
    }

    bool ended_inside = (aend == n_atoms) || (__ldg(mem + aend) != seg);
    int tseg = -1;
    if (ended_inside) {
        if (began_inside) store_full(seg);
        else              buffer_head(seg, 0);
    } else {
        if (began_inside) tseg = seg;            // tail owner: current regs
        else              buffer_head(seg, 1);   // pass-through chunk
    }

    // ---- publish all boundary records now (L2-hot for gg_combine) ----
    if (tseg >= 0) {
        float2 a2 = unpack2(s01), b2 = unpack2(s23);
        g_sT[wg][lane] = make_float4(a2.x, a2.y, b2.x, b2.y);
        g_mT[wg][lane] = m;
        if (lane == 0) g_cT[wg] = cnt;
    }
    if (hseg >= 0) {
        g_sH[wg][lane] = hsum;
        g_mH[wg][lane] = hmax;
        if (lane == 0) { g_cH[wg] = hcnt; g_ptH[wg] = hpt; }
    }
    if (lane == 0) { g_segT[wg] = tseg; g_segH[wg] = hseg; }
}

// ---------------------------------------------------------------------------
// Combine: one warp per owner record. Merge tail[w] with head[w+1...] chain,
// then write the straddling segment's output row (exactly once).
// ---------------------------------------------------------------------------
__global__ void gg_combine(float* __restrict__ out, int nwarps) {
    int t = blockIdx.x * blockDim.x + threadIdx.x;
    int w = t >> 5, lane = t & 31;
    if (w >= nwarps) return;
    int seg = g_segT[w];
    if (seg < 0) return;

    float4 s = g_sT[w][lane];
    float4 m = g_mT[w][lane];
    int  cnt = g_cT[w];

    for (int j = w + 1; j < nwarps; ++j) {
        if (g_segH[j] != seg) break;
        float4 hs = g_sH[j][lane], hm = g_mH[j][lane];
        s.x += hs.x; s.y += hs.y; s.z += hs.z; s.w += hs.w;
        m.x = fmaxf(m.x, hm.x); m.y = fmaxf(m.y, hm.y);
        m.z = fmaxf(m.z, hm.z); m.w = fmaxf(m.w, hm.w);
        cnt += g_cH[j];
        if (!g_ptH[j]) break;   // segment ended inside warp j
    }

    float r = 1.0f / (float)cnt;
    float* om = out + (size_t)seg * 256 + lane * 4;
    *(float4*)om         = make_float4(s.x * r, s.y * r, s.z * r, s.w * r);
    *(float4*)(om + 128) = m;
}

// ---------------------------------------------------------------------------
extern "C" void kernel_launch(void* const* d_in, const int* in_sizes, int n_in,
                              void* d_out, int out_size) {
    const float* feat = (const float*)d_in[0];
    const int*   mem  = (const int*)d_in[1];
    float*       out  = (float*)d_out;

    int n_atoms = in_sizes[1];          // membership element count

    // Exactly-balanced single wave: SM_count * BLOCKS_PER_SM blocks, 8 warps each.
    int sm_count = 152;
    cudaDeviceGetAttribute(&sm_count, cudaDevAttrMultiProcessorCount, 0);
    int nblocks = sm_count * BLOCKS_PER_SM;
    int max_blocks = MAXW / (THREADS_MAIN / 32);
    if (nblocks > max_blocks) nblocks = max_blocks;
    int nwarps = nblocks * (THREADS_MAIN / 32);
    long long chunk_ll = ((long long)n_atoms + nwarps - 1) / nwarps;
    int chunk = (int)((chunk_ll + 7) / 8) * 8;   // multiple of 8 (int4 alignment)

    gg_main<<<nblocks, THREADS_MAIN>>>(feat, mem, out, n_atoms, chunk);

    int comb_threads = nwarps * 32;
    gg_combine<<<(comb_threads + 255) / 256, 256>>>(out, nwarps);
}

// round 10
// speedup vs baseline: 1.0503x; 1.0216x over previous
#include <cuda_runtime.h>
#include <math_constants.h>

#define THREADS_MAIN 256    // 8 warps per block
#define BLOCKS_PER_SM 2
#define MAXW 4096           // max warps supported (grid capped accordingly)

// Head partial records + publish flags (fully rewritten every launch).
__device__ float4 g_sH[MAXW][32];   // head partial sums
__device__ float4 g_mH[MAXW][32];   // head partial maxs
__device__ int    g_cH[MAXW];       // head partial count
__device__ int    g_segH[MAXW];     // head segment id (-1 = none)
__device__ int    g_ptH[MAXW];      // head is pass-through (open both ends)
__device__ int    g_ready[MAXW];    // publish flag (0 -> 1 after threadfence)

__device__ __forceinline__ void f32x2_add(unsigned long long& acc, unsigned long long v) {
    asm("add.rn.f32x2 %0, %0, %1;" : "+l"(acc) : "l"(v));
}
__device__ __forceinline__ float2 unpack2(unsigned long long v) {
    float a, b;
    asm("mov.b64 {%0,%1}, %2;" : "=f"(a), "=f"(b) : "l"(v));
    return make_float2(a, b);
}

// ---------------------------------------------------------------------------
// Single fused kernel. Warp-per-chunk segmented scan (lane l owns features
// [4l,4l+4)). Interior segments -> direct store with mean divided in place.
// A segment straddling chunk ends is OWNED by the warp containing its first
// atom: later warps publish register-buffered head partials (+ threadfence +
// ready flag); the owner spins on the flags, merges via L2 (__ldcg), and
// writes the row exactly once. Grid = one resident wave -> spin is safe.
// ---------------------------------------------------------------------------
__global__ void __launch_bounds__(THREADS_MAIN)
gg_main(const float* __restrict__ feat,
        const int*   __restrict__ mem,
        float*       __restrict__ out,
        int n_atoms, int chunk, int nwarps) {
    const int lane = threadIdx.x & 31;
    const int wg   = (blockIdx.x * blockDim.x + threadIdx.x) >> 5;

    // Reset my publish flag long before any reader can arrive (readers spin
    // only after scanning their full ~860-atom chunk; dispatch skew << that).
    if (lane == 0) g_ready[wg] = 0;
    __syncwarp();

    long long astart = (long long)wg * chunk;
    if (astart >= n_atoms) {
        if (lane == 0) { g_segH[wg] = -1; __threadfence(); g_ready[wg] = 1; }
        return;
    }
    long long aend = astart + chunk;
    if (aend > n_atoms) aend = n_atoms;

    const ulonglong2* __restrict__ frow = (const ulonglong2*)feat;  // 32 per row

    int  seg = __ldg(mem + astart);
    bool began_inside = (astart == 0) || (__ldg(mem + astart - 1) != seg);

    unsigned long long s01 = 0, s23 = 0;   // packed f32x2 sums
    float4 m = make_float4(-CUDART_INF_F, -CUDART_INF_F, -CUDART_INF_F, -CUDART_INF_F);
    int cnt = 0;

    // Head partial buffered in registers until the end.
    int    hseg = -1, hpt = 0, hcnt = 0;
    float4 hsum = make_float4(0.f, 0.f, 0.f, 0.f);
    float4 hmax = hsum;

    auto store_full = [&](int sg) {
        float2 a = unpack2(s01), b = unpack2(s23);
        float r = 1.0f / (float)cnt;
        float* om = out + (size_t)sg * 256 + lane * 4;
        *(float4*)om         = make_float4(a.x * r, a.y * r, b.x * r, b.y * r);
        *(float4*)(om + 128) = m;
    };
    auto buffer_head = [&](int sg, int pt) {
        float2 a = unpack2(s01), b = unpack2(s23);
        hsum = make_float4(a.x, a.y, b.x, b.y);
        hmax = m; hcnt = cnt; hseg = sg; hpt = pt;
    };
    auto flush_mid = [&](int sg) {       // segment ended inside the chunk
        if (began_inside) store_full(sg);
        else              buffer_head(sg, 0);
        began_inside = true;
    };
    auto reset = [&]() {
        s01 = 0; s23 = 0;
        m = make_float4(-CUDART_INF_F, -CUDART_INF_F, -CUDART_INF_F, -CUDART_INF_F);
        cnt = 0;
    };
    auto accum = [&](ulonglong2 v) {
        f32x2_add(s01, v.x);
        f32x2_add(s23, v.y);
        float2 a = unpack2(v.x), b = unpack2(v.y);
        m.x = fmaxf(m.x, a.x); m.y = fmaxf(m.y, a.y);
        m.z = fmaxf(m.z, b.x); m.w = fmaxf(m.w, b.y);
    };

    long long a = astart;
    for (; a + 8 <= aend; a += 8) {
        int4 mb0 = *(const int4*)(mem + a);
        int4 mb1 = *(const int4*)(mem + a + 4);
        ulonglong2 vv[8];
#pragma unroll
        for (int u = 0; u < 8; ++u)
            vv[u] = __ldg(&frow[(a + u) * 32 + lane]);

        if (mb0.x == mb1.w) {
            // whole 8-batch is one segment (membership sorted)
            if (mb0.x != seg) { flush_mid(seg); seg = mb0.x; reset(); }
#pragma unroll
            for (int u = 0; u < 8; ++u) accum(vv[u]);
            cnt += 8;
        } else {
            int mbs[8] = {mb0.x, mb0.y, mb0.z, mb0.w, mb1.x, mb1.y, mb1.z, mb1.w};
#pragma unroll
            for (int u = 0; u < 8; ++u) {
                if (mbs[u] != seg) { flush_mid(seg); seg = mbs[u]; reset(); }
                accum(vv[u]);
                ++cnt;
            }
        }
    }
    for (; a < aend; ++a) {     // scalar tail (last active warp only)
        int mb = __ldg(mem + a);
        ulonglong2 v = __ldg(&frow[a * 32 + lane]);
        if (mb != seg) { flush_mid(seg); seg = mb; reset(); }
        accum(v);
        ++cnt;
    }

    bool ended_inside = (aend == n_atoms) || (__ldg(mem + aend) != seg);
    int tseg = -1;
    if (ended_inside) {
        if (began_inside) store_full(seg);
        else              buffer_head(seg, 0);
    } else {
        if (began_inside) tseg = seg;            // this warp owns the straddler
        else              buffer_head(seg, 1);   // pass-through chunk
    }

    // ---- publish head record, then ready flag (release) ----
    if (hseg >= 0) {
        g_sH[wg][lane] = hsum;
        g_mH[wg][lane] = hmax;
        if (lane == 0) { g_cH[wg] = hcnt; g_ptH[wg] = hpt; }
    }
    if (lane == 0) g_segH[wg] = hseg;
    __threadfence();
    if (lane == 0) ((volatile int*)g_ready)[wg] = 1;

    // ---- owner combines its straddling segment in-kernel ----
    if (tseg >= 0) {
        float2 x = unpack2(s01), y = unpack2(s23);
        float4 S = make_float4(x.x, x.y, y.x, y.y);
        float4 M = m;
        int    C = cnt;
        for (int j = wg + 1; j < nwarps; ++j) {
            if (lane == 0) {
                while (((volatile int*)g_ready)[j] == 0) __nanosleep(64);
            }
            __syncwarp();
            __threadfence();                      // acquire
            if (__ldcg(&g_segH[j]) != tseg) break;
            float4 hs = __ldcg(&g_sH[j][lane]);
            float4 hm = __ldcg(&g_mH[j][lane]);
            S.x += hs.x; S.y += hs.y; S.z += hs.z; S.w += hs.w;
            M.x = fmaxf(M.x, hm.x); M.y = fmaxf(M.y, hm.y);
            M.z = fmaxf(M.z, hm.z); M.w = fmaxf(M.w, hm.w);
            C += __ldcg(&g_cH[j]);
            if (!__ldcg(&g_ptH[j])) break;        // segment ended inside warp j
        }
        float r = 1.0f / (float)C;
        float* om = out + (size_t)tseg * 256 + lane * 4;
        *(float4*)om         = make_float4(S.x * r, S.y * r, S.z * r, S.w * r);
        *(float4*)(om + 128) = M;
    }
}

// ---------------------------------------------------------------------------
extern "C" void kernel_launch(void* const* d_in, const int* in_sizes, int n_in,
                              void* d_out, int out_size) {
    const float* feat = (const float*)d_in[0];
    const int*   mem  = (const int*)d_in[1];
    float*       out  = (float*)d_out;

    int n_atoms = in_sizes[1];          // membership element count

    // Exactly one resident wave: SM_count * BLOCKS_PER_SM blocks, 8 warps each.
    int sm_count = 152;
    cudaDeviceGetAttribute(&sm_count, cudaDevAttrMultiProcessorCount, 0);
    int nblocks = sm_count * BLOCKS_PER_SM;
    int max_blocks = MAXW / (THREADS_MAIN / 32);
    if (nblocks > max_blocks) nblocks = max_blocks;
    int nwarps = nblocks * (THREADS_MAIN / 32);
    long long chunk_ll = ((long long)n_atoms + nwarps - 1) / nwarps;
    int chunk = (int)((chunk_ll + 7) / 8) * 8;   // multiple of 8 (int4 alignment)

    gg_main<<<nblocks, THREADS_MAIN>>>(feat, mem, out, n_atoms, chunk, nwarps);
}